// round 1
// baseline (speedup 1.0000x reference)
#include <cuda_runtime.h>

// ---------------------------------------------------------------------------
// Kernel 1: zero the whole output (62.98 MB). Pure HBM-store-bound.
// ---------------------------------------------------------------------------
__global__ void wg_zero(float4* __restrict__ out, int n4) {
    int i = blockIdx.x * blockDim.x + threadIdx.x;
    if (i < n4) out[i] = make_float4(0.f, 0.f, 0.f, 0.f);
}

// ---------------------------------------------------------------------------
// Kernel 2: compute the only nonzero strip: out[b, 0, 0:2, 0:62] for all b.
//   31 blocks = tiles u, 64 threads = channels c.
//   Per thread: U = G W G^T (f=0 filter), V = B^T X B with X = x[0,c,0:4,2u:2u+4],
//   M_c = U .* V, reduce over c, then Y = AT M AT^T, fan out to 64 batches.
// ---------------------------------------------------------------------------
__global__ void wg_strip(const float* __restrict__ x,
                         const float* __restrict__ filt,
                         float* __restrict__ out) {
    const int u = blockIdx.x;   // tile column 0..30
    const int c = threadIdx.x;  // channel 0..63

    // W = filters[0, c, :, :]
    float W[3][3];
#pragma unroll
    for (int j = 0; j < 3; ++j)
#pragma unroll
        for (int k = 0; k < 3; ++k)
            W[j][k] = filt[c * 9 + j * 3 + k];

    // U = G W G^T,  G = [[1,0,0],[.5,.5,1.2],[.5,-.5,.5],[0,0,1]]
    float s[4][3];
#pragma unroll
    for (int k = 0; k < 3; ++k) {
        s[0][k] = W[0][k];
        s[1][k] = 0.5f * W[0][k] + 0.5f * W[1][k] + 1.2f * W[2][k];
        s[2][k] = 0.5f * W[0][k] - 0.5f * W[1][k] + 0.5f * W[2][k];
        s[3][k] = W[2][k];
    }
    float U[4][4];
#pragma unroll
    for (int i = 0; i < 4; ++i) {
        U[i][0] = s[i][0];
        U[i][1] = 0.5f * s[i][0] + 0.5f * s[i][1] + 1.2f * s[i][2];
        U[i][2] = 0.5f * s[i][0] - 0.5f * s[i][1] + 0.5f * s[i][2];
        U[i][3] = s[i][2];
    }

    // X = x[0, c, 0:4, 2u : 2u+4]   (x is (64,64,64,64), b=0)
    float X[4][4];
    const float* xp = x + c * 4096 + 2 * u;
#pragma unroll
    for (int j = 0; j < 4; ++j)
#pragma unroll
        for (int k = 0; k < 4; ++k)
            X[j][k] = xp[j * 64 + k];

    // t = B^T X ; B = [[1,0,-1,0],[0,1,1,0],[0,-1,1,0],[0,1,0,-1]]
    // B^T rows: (1,0,0,0) (0,1,-1,1) (-1,1,1,0) (0,0,0,-1)
    float t[4][4];
#pragma unroll
    for (int k = 0; k < 4; ++k) {
        t[0][k] = X[0][k];
        t[1][k] = X[1][k] - X[2][k] + X[3][k];
        t[2][k] = -X[0][k] + X[1][k] + X[2][k];
        t[3][k] = -X[3][k];
    }
    // V = t B ; B cols: (1,0,0,0) (0,1,-1,1) (-1,1,1,0) (0,0,0,-1)
    // M_c = U .* V, accumulate across channels
    float Macc[16];
#pragma unroll
    for (int i = 0; i < 4; ++i) {
        float v0 = t[i][0];
        float v1 = t[i][1] - t[i][2] + t[i][3];
        float v2 = -t[i][0] + t[i][1] + t[i][2];
        float v3 = -t[i][3];
        Macc[i * 4 + 0] = U[i][0] * v0;
        Macc[i * 4 + 1] = U[i][1] * v1;
        Macc[i * 4 + 2] = U[i][2] * v2;
        Macc[i * 4 + 3] = U[i][3] * v3;
    }

    // reduce the 16 values across the 64 threads (2 warps)
#pragma unroll
    for (int off = 16; off > 0; off >>= 1)
#pragma unroll
        for (int e = 0; e < 16; ++e)
            Macc[e] += __shfl_down_sync(0xffffffffu, Macc[e], off);

    __shared__ float sm[2][16];
    __shared__ float Y[4];
    const int warp = threadIdx.x >> 5;
    const int lane = threadIdx.x & 31;
    if (lane == 0) {
#pragma unroll
        for (int e = 0; e < 16; ++e) sm[warp][e] = Macc[e];
    }
    __syncthreads();
    if (threadIdx.x == 0) {
        float M[4][4];
#pragma unroll
        for (int e = 0; e < 16; ++e) M[e >> 2][e & 3] = sm[0][e] + sm[1][e];
        // Y = AT M AT^T ; AT = [[1,1,1,0],[0,1,-1,-1]]
        float T0[4], T1[4];
#pragma unroll
        for (int k = 0; k < 4; ++k) {
            T0[k] = M[0][k] + M[1][k] + M[2][k];
            T1[k] = M[1][k] - M[2][k] - M[3][k];
        }
        Y[0] = T0[0] + T0[1] + T0[2];   // (i=0,l=0)
        Y[1] = T0[1] - T0[2] - T0[3];   // (i=0,l=1)
        Y[2] = T1[0] + T1[1] + T1[2];   // (i=1,l=0)
        Y[3] = T1[1] - T1[2] - T1[3];   // (i=1,l=1)
    }
    __syncthreads();

    // fan out: out[b, 0, i, 2u+l] for every batch b; thread = b
    // out layout (64, 64, 62, 62): batch stride 64*62*62 = 246016, f=0.
    const int b = threadIdx.x;
    float* op = out + (size_t)b * 246016 + 2 * u;
    op[0]  = Y[0];
    op[1]  = Y[1];
    op[62] = Y[2];
    op[63] = Y[3];
}

extern "C" void kernel_launch(void* const* d_in, const int* in_sizes, int n_in,
                              void* d_out, int out_size) {
    const float* x    = (const float*)d_in[0];   // (64,64,64,64) f32
    const float* filt = (const float*)d_in[1];   // (64,64,3,3)   f32
    float* out = (float*)d_out;                  // (64,64,62,62) f32

    // out_size = 64*64*62*62 = 15,745,024 — divisible by 4, 256B-aligned base.
    const int n4 = out_size / 4;
    wg_zero<<<(n4 + 255) / 256, 256>>>((float4*)d_out, n4);
    wg_strip<<<31, 64>>>(x, filt, out);
}

// round 2
// speedup vs baseline: 1.3008x; 1.3008x over previous
#include <cuda_runtime.h>

// Output (64, 64, 62, 62) f32. Only out[b, 0, 0:2, 0:62] is nonzero — that is
// the first 124 floats (= 31 float4s, aligned) of every batch slice.
// One fused kernel:
//   blocks [0, 31)        : compute the 2x62 strip for tile u = blockIdx.x
//   blocks [31, 31+15424) : zero-fill everything EXCEPT the strip words
// No overlap between the two write sets -> no race, single launch.

#define BATCH_F4   61504   // 246016 floats / 4 per batch slice
#define STRIP_F4   31      // first 31 float4s of each batch = the strip
#define ZBLK_PER_B 241     // ceil((61504-31)/256)
#define NSTRIP     31

__global__ void wg_fused(const float* __restrict__ x,
                         const float* __restrict__ filt,
                         float* __restrict__ out) {
    if (blockIdx.x >= NSTRIP) {
        // ---------------- zero-fill path ----------------
        const int zb    = blockIdx.x - NSTRIP;
        const int batch = zb / ZBLK_PER_B;
        const int chunk = zb % ZBLK_PER_B;
        const int i = STRIP_F4 + chunk * 256 + threadIdx.x;  // skip strip words
        if (i < BATCH_F4) {
            float4* o4 = (float4*)out;
            o4[(size_t)batch * BATCH_F4 + i] = make_float4(0.f, 0.f, 0.f, 0.f);
        }
        return;
    }

    // ---------------- strip path: tile u = blockIdx.x ----------------
    const int u = blockIdx.x;       // 0..30
    __shared__ float sm[2][16];
    __shared__ float Y[4];

    if (threadIdx.x < 64) {
        const int c = threadIdx.x;  // channel

        // W = filters[0, c]
        float W[3][3];
#pragma unroll
        for (int j = 0; j < 3; ++j)
#pragma unroll
            for (int k = 0; k < 3; ++k)
                W[j][k] = filt[c * 9 + j * 3 + k];

        // U = G W G^T,  G = [[1,0,0],[.5,.5,1.2],[.5,-.5,.5],[0,0,1]]
        float s[4][3];
#pragma unroll
        for (int k = 0; k < 3; ++k) {
            s[0][k] = W[0][k];
            s[1][k] = 0.5f * W[0][k] + 0.5f * W[1][k] + 1.2f * W[2][k];
            s[2][k] = 0.5f * W[0][k] - 0.5f * W[1][k] + 0.5f * W[2][k];
            s[3][k] = W[2][k];
        }
        float U[4][4];
#pragma unroll
        for (int i = 0; i < 4; ++i) {
            U[i][0] = s[i][0];
            U[i][1] = 0.5f * s[i][0] + 0.5f * s[i][1] + 1.2f * s[i][2];
            U[i][2] = 0.5f * s[i][0] - 0.5f * s[i][1] + 0.5f * s[i][2];
            U[i][3] = s[i][2];
        }

        // X = x[0, c, 0:4, 2u:2u+4]
        float X[4][4];
        const float* xp = x + c * 4096 + 2 * u;
#pragma unroll
        for (int j = 0; j < 4; ++j)
#pragma unroll
            for (int k = 0; k < 4; ++k)
                X[j][k] = xp[j * 64 + k];

        // t = B^T X ; B^T rows: (1,0,0,0) (0,1,-1,1) (-1,1,1,0) (0,0,0,-1)
        float t[4][4];
#pragma unroll
        for (int k = 0; k < 4; ++k) {
            t[0][k] = X[0][k];
            t[1][k] = X[1][k] - X[2][k] + X[3][k];
            t[2][k] = -X[0][k] + X[1][k] + X[2][k];
            t[3][k] = -X[3][k];
        }
        // V = t B ; M_c = U .* V
        float Macc[16];
#pragma unroll
        for (int i = 0; i < 4; ++i) {
            float v0 = t[i][0];
            float v1 = t[i][1] - t[i][2] + t[i][3];
            float v2 = -t[i][0] + t[i][1] + t[i][2];
            float v3 = -t[i][3];
            Macc[i * 4 + 0] = U[i][0] * v0;
            Macc[i * 4 + 1] = U[i][1] * v1;
            Macc[i * 4 + 2] = U[i][2] * v2;
            Macc[i * 4 + 3] = U[i][3] * v3;
        }

        // reduce 16 values over 64 channels (2 warps)
#pragma unroll
        for (int off = 16; off > 0; off >>= 1)
#pragma unroll
            for (int e = 0; e < 16; ++e)
                Macc[e] += __shfl_down_sync(0xffffffffu, Macc[e], off);

        const int warp = threadIdx.x >> 5;
        const int lane = threadIdx.x & 31;
        if (lane == 0) {
#pragma unroll
            for (int e = 0; e < 16; ++e) sm[warp][e] = Macc[e];
        }
    }
    __syncthreads();
    if (threadIdx.x == 0) {
        float M[4][4];
#pragma unroll
        for (int e = 0; e < 16; ++e) M[e >> 2][e & 3] = sm[0][e] + sm[1][e];
        // Y = AT M AT^T ; AT = [[1,1,1,0],[0,1,-1,-1]]
        float T0[4], T1[4];
#pragma unroll
        for (int k = 0; k < 4; ++k) {
            T0[k] = M[0][k] + M[1][k] + M[2][k];
            T1[k] = M[1][k] - M[2][k] - M[3][k];
        }
        Y[0] = T0[0] + T0[1] + T0[2];
        Y[1] = T0[1] - T0[2] - T0[3];
        Y[2] = T1[0] + T1[1] + T1[2];
        Y[3] = T1[1] - T1[2] - T1[3];
    }
    __syncthreads();

    // fan out to all 64 batches: out[b, 0, {0,1}, 2u+{0,1}]
    if (threadIdx.x < 64) {
        const int b = threadIdx.x;
        float* op = out + (size_t)b * 246016 + 2 * u;
        op[0]  = Y[0];
        op[1]  = Y[1];
        op[62] = Y[2];
        op[63] = Y[3];
    }
}

extern "C" void kernel_launch(void* const* d_in, const int* in_sizes, int n_in,
                              void* d_out, int out_size) {
    const float* x    = (const float*)d_in[0];   // (64,64,64,64) f32
    const float* filt = (const float*)d_in[1];   // (64,64,3,3)   f32
    float* out = (float*)d_out;                  // (64,64,62,62) f32

    const int nblocks = NSTRIP + ZBLK_PER_B * 64;  // 31 + 15424
    wg_fused<<<nblocks, 256>>>(x, filt, out);
}